// round 3
// baseline (speedup 1.0000x reference)
#include <cuda_runtime.h>
#include <math.h>

#define NMAX 100000
#define EMAX 1600000
#define FDIM 128
#define NHEAD 4
#define NEG_SLOPE 0.2f
#define SCAN_CHUNK 1024

// Scratch (device globals: allocation-free rule)
__device__ float g_h[NMAX * FDIM];       // x @ W   [N,128]
__device__ float g_si[NMAX * NHEAD];     // per-node src-side score   [N,4]
__device__ float g_sj[NMAX * NHEAD];     // per-node dst-side score   [N,4]
__device__ int   g_cnt[NMAX];            // per-node non-self in-degree
__device__ int   g_off[NMAX];            // CSR row start
__device__ int   g_cur[NMAX];            // scatter cursor (== row end after scatter)
__device__ int   g_part[128];            // scan partials
__device__ int   g_col[EMAX];            // CSR column (neighbor j) indices

__device__ __forceinline__ float lrelu(float v) {
    return v > 0.0f ? v : NEG_SLOPE * v;
}

// ---------------------------------------------------------------------------
// Kernel 1: h = x @ W  (128x128 tile SGEMM) + fused s_i/s_j epilogue
// ---------------------------------------------------------------------------
__global__ __launch_bounds__(256) void gemm_kernel(const float* __restrict__ x,
                                                   const float* __restrict__ w,
                                                   const float* __restrict__ att,
                                                   int N) {
    __shared__ float As[16][128];
    __shared__ float Bs[16 * 128];
    __shared__ float si_s[128][4];
    __shared__ float sj_s[128][4];

    const int t = threadIdx.x;
    const int nb = blockIdx.x * 128;
    const int tx = t & 15;
    const int ty = t >> 4;
    const int ln = t >> 1;
    const int lhalf = t & 1;

    // zero the score-reduction buffers (visible after first __syncthreads in loop)
    for (int i = t; i < 512; i += 256) {
        ((float*)si_s)[i] = 0.0f;
        ((float*)sj_s)[i] = 0.0f;
    }

    float acc[8][8];
    #pragma unroll
    for (int i = 0; i < 8; i++)
        #pragma unroll
        for (int j = 0; j < 8; j++) acc[i][j] = 0.0f;

    for (int kc = 0; kc < 128; kc += 16) {
        float4 a0 = make_float4(0.f, 0.f, 0.f, 0.f);
        float4 a1 = make_float4(0.f, 0.f, 0.f, 0.f);
        const int gn = nb + ln;
        if (gn < N) {
            const float4* xp = reinterpret_cast<const float4*>(x + (size_t)gn * 128 + kc + lhalf * 8);
            a0 = xp[0];
            a1 = xp[1];
        }
        const float4* wp = reinterpret_cast<const float4*>(w + kc * 128);
        float4 b0 = wp[t];
        float4 b1 = wp[t + 256];

        __syncthreads();
        const int k0 = lhalf * 8;
        As[k0 + 0][ln] = a0.x; As[k0 + 1][ln] = a0.y;
        As[k0 + 2][ln] = a0.z; As[k0 + 3][ln] = a0.w;
        As[k0 + 4][ln] = a1.x; As[k0 + 5][ln] = a1.y;
        As[k0 + 6][ln] = a1.z; As[k0 + 7][ln] = a1.w;
        reinterpret_cast<float4*>(Bs)[t] = b0;
        reinterpret_cast<float4*>(Bs)[t + 256] = b1;
        __syncthreads();

        #pragma unroll
        for (int k = 0; k < 16; k++) {
            float4 av0 = *reinterpret_cast<const float4*>(&As[k][ty * 8]);
            float4 av1 = *reinterpret_cast<const float4*>(&As[k][ty * 8 + 4]);
            float4 bv0 = *reinterpret_cast<const float4*>(&Bs[k * 128 + tx * 8]);
            float4 bv1 = *reinterpret_cast<const float4*>(&Bs[k * 128 + tx * 8 + 4]);
            float a[8] = {av0.x, av0.y, av0.z, av0.w, av1.x, av1.y, av1.z, av1.w};
            float b[8] = {bv0.x, bv0.y, bv0.z, bv0.w, bv1.x, bv1.y, bv1.z, bv1.w};
            #pragma unroll
            for (int i = 0; i < 8; i++)
                #pragma unroll
                for (int j = 0; j < 8; j++)
                    acc[i][j] = fmaf(a[i], b[j], acc[i][j]);
        }
    }

    // store h
    #pragma unroll
    for (int i = 0; i < 8; i++) {
        const int gn = nb + ty * 8 + i;
        if (gn < N) {
            float4* hp = reinterpret_cast<float4*>(g_h + (size_t)gn * 128 + tx * 8);
            hp[0] = make_float4(acc[i][0], acc[i][1], acc[i][2], acc[i][3]);
            hp[1] = make_float4(acc[i][4], acc[i][5], acc[i][6], acc[i][7]);
        }
    }

    // epilogue: per-row, per-head attention partials
    // this thread's 8 cols tx*8..tx*8+7 lie inside head q = tx>>2, channels ch0..ch0+7
    {
        const int q = tx >> 2;
        const int ch0 = (tx & 3) * 8;
        float ai[8], aj[8];
        #pragma unroll
        for (int j = 0; j < 8; j++) {
            ai[j] = __ldg(att + q * 64 + ch0 + j);
            aj[j] = __ldg(att + q * 64 + 32 + ch0 + j);
        }
        #pragma unroll
        for (int i = 0; i < 8; i++) {
            float psi = 0.f, psj = 0.f;
            #pragma unroll
            for (int j = 0; j < 8; j++) {
                psi = fmaf(acc[i][j], ai[j], psi);
                psj = fmaf(acc[i][j], aj[j], psj);
            }
            atomicAdd(&si_s[ty * 8 + i][q], psi);
            atomicAdd(&sj_s[ty * 8 + i][q], psj);
        }
    }
    __syncthreads();
    for (int i = t; i < 512; i += 256) {
        const int r = i >> 2, q = i & 3;
        const int gn = nb + r;
        if (gn < N) {
            g_si[gn * 4 + q] = si_s[r][q];
            g_sj[gn * 4 + q] = sj_s[r][q];
        }
    }
}

// ---------------------------------------------------------------------------
// CSR build: zero -> histogram -> 2-level exclusive scan -> scatter
// ---------------------------------------------------------------------------
__global__ __launch_bounds__(256) void zero_cnt_kernel(int N) {
    const int i = blockIdx.x * blockDim.x + threadIdx.x;
    if (i < N) g_cnt[i] = 0;
}

__global__ __launch_bounds__(256) void hist_kernel(const int* __restrict__ src,
                                                   const int* __restrict__ dst, int E) {
    const int e = blockIdx.x * blockDim.x + threadIdx.x;
    if (e >= E) return;
    const int r = __ldg(src + e), c = __ldg(dst + e);
    if (r != c) atomicAdd(&g_cnt[r], 1);
}

// per-chunk (1024) sums
__global__ __launch_bounds__(256) void scan_partial_kernel(int N) {
    const int b = blockIdx.x, t = threadIdx.x;
    int s = 0;
    #pragma unroll
    for (int j = 0; j < 4; j++) {
        const int i = b * SCAN_CHUNK + t * 4 + j;
        if (i < N) s += g_cnt[i];
    }
    #pragma unroll
    for (int off = 16; off > 0; off >>= 1) s += __shfl_xor_sync(0xFFFFFFFFu, s, off);
    __shared__ int ws[8];
    if ((t & 31) == 0) ws[t >> 5] = s;
    __syncthreads();
    if (t == 0) {
        int tot = 0;
        #pragma unroll
        for (int wdx = 0; wdx < 8; wdx++) tot += ws[wdx];
        g_part[b] = tot;
    }
}

// single-block exclusive scan of partials (NBLK <= 128)
__global__ __launch_bounds__(128) void scan_top_kernel(int nblk) {
    const int t = threadIdx.x;
    const int lane = t & 31, wdx = t >> 5;
    int v = (t < nblk) ? g_part[t] : 0;
    int x = v;
    #pragma unroll
    for (int d = 1; d < 32; d <<= 1) {
        int y = __shfl_up_sync(0xFFFFFFFFu, x, d);
        if (lane >= d) x += y;
    }
    __shared__ int ws[4];
    if (lane == 31) ws[wdx] = x;
    __syncthreads();
    __shared__ int woff[4];
    if (t == 0) {
        int run = 0;
        #pragma unroll
        for (int i = 0; i < 4; i++) { woff[i] = run; run += ws[i]; }
    }
    __syncthreads();
    if (t < nblk) g_part[t] = x - v + woff[wdx];  // exclusive
}

// per-chunk exclusive scan + global offset -> g_off, g_cur
__global__ __launch_bounds__(256) void scan_low_kernel(int N) {
    const int b = blockIdx.x, t = threadIdx.x;
    const int lane = t & 31, wdx = t >> 5;
    int v[4];
    int base_i = b * SCAN_CHUNK + t * 4;
    #pragma unroll
    for (int j = 0; j < 4; j++) v[j] = (base_i + j < N) ? g_cnt[base_i + j] : 0;
    int tsum = v[0] + v[1] + v[2] + v[3];
    int x = tsum;
    #pragma unroll
    for (int d = 1; d < 32; d <<= 1) {
        int y = __shfl_up_sync(0xFFFFFFFFu, x, d);
        if (lane >= d) x += y;
    }
    __shared__ int ws[8], woff[8];
    if (lane == 31) ws[wdx] = x;
    __syncthreads();
    if (t == 0) {
        int run = 0;
        #pragma unroll
        for (int i = 0; i < 8; i++) { woff[i] = run; run += ws[i]; }
    }
    __syncthreads();
    int excl = (x - tsum) + woff[wdx] + g_part[b];
    #pragma unroll
    for (int j = 0; j < 4; j++) {
        const int i = base_i + j;
        if (i < N) { g_off[i] = excl; g_cur[i] = excl; }
        excl += v[j];
    }
}

__global__ __launch_bounds__(256) void scatter_kernel(const int* __restrict__ src,
                                                      const int* __restrict__ dst, int E) {
    const int e = blockIdx.x * blockDim.x + threadIdx.x;
    if (e >= E) return;
    const int r = __ldg(src + e), c = __ldg(dst + e);
    if (r != c) {
        const int pos = atomicAdd(&g_cur[r], 1);
        g_col[pos] = c;
    }
}

// ---------------------------------------------------------------------------
// Aggregation: one warp per node. Register accumulation, softmax divide + bias
// fused. coef computed in lanes 0..3, broadcast via shfl.
// ---------------------------------------------------------------------------
__global__ __launch_bounds__(256) void agg_kernel(const float* __restrict__ bias,
                                                  float* __restrict__ out, int N) {
    const int n = (blockIdx.x * blockDim.x + threadIdx.x) >> 5;
    if (n >= N) return;
    const int lane = threadIdx.x & 31;

    const float s_i = (lane < 4) ? g_si[n * 4 + lane] : 0.0f;

    float acc[NHEAD], dsum[NHEAD];
    // self-loop term
    {
        float e = 0.0f;
        if (lane < 4) e = expf(lrelu(s_i + g_sj[n * 4 + lane]));
        const float* hp = g_h + (size_t)n * 128;
        #pragma unroll
        for (int q = 0; q < NHEAD; q++) {
            const float cf = __shfl_sync(0xFFFFFFFFu, e, q);
            acc[q] = cf * __ldg(hp + q * 32 + lane);
            dsum[q] = cf;
        }
    }

    int k = g_off[n];
    const int end = g_cur[n];

    // 2-way unrolled neighbor loop for MLP
    for (; k + 2 <= end; k += 2) {
        const int cA = __ldg(g_col + k);
        const int cB = __ldg(g_col + k + 1);
        float eA = 0.0f, eB = 0.0f;
        if (lane < 4) {
            eA = expf(lrelu(s_i + __ldg(g_sj + cA * 4 + lane)));
            eB = expf(lrelu(s_i + __ldg(g_sj + cB * 4 + lane)));
        }
        const float* hA = g_h + (size_t)cA * 128;
        const float* hB = g_h + (size_t)cB * 128;
        #pragma unroll
        for (int q = 0; q < NHEAD; q++) {
            const float cfA = __shfl_sync(0xFFFFFFFFu, eA, q);
            const float cfB = __shfl_sync(0xFFFFFFFFu, eB, q);
            acc[q] = fmaf(cfA, __ldg(hA + q * 32 + lane), acc[q]);
            acc[q] = fmaf(cfB, __ldg(hB + q * 32 + lane), acc[q]);
            dsum[q] += cfA + cfB;
        }
    }
    if (k < end) {
        const int c = __ldg(g_col + k);
        float e = 0.0f;
        if (lane < 4) e = expf(lrelu(s_i + __ldg(g_sj + c * 4 + lane)));
        const float* hp = g_h + (size_t)c * 128;
        #pragma unroll
        for (int q = 0; q < NHEAD; q++) {
            const float cf = __shfl_sync(0xFFFFFFFFu, e, q);
            acc[q] = fmaf(cf, __ldg(hp + q * 32 + lane), acc[q]);
            dsum[q] += cf;
        }
    }

    float* orow = out + (size_t)n * 128;
    #pragma unroll
    for (int q = 0; q < NHEAD; q++) {
        const float d = fmaxf(dsum[q], 1e-16f);
        orow[q * 32 + lane] = acc[q] / d + __ldg(bias + q * 32 + lane);
    }
}

// ---------------------------------------------------------------------------
extern "C" void kernel_launch(void* const* d_in, const int* in_sizes, int n_in,
                              void* d_out, int out_size) {
    const float* x    = (const float*)d_in[0];
    const int*   ei   = (const int*)d_in[1];
    const float* w    = (const float*)d_in[2];
    const float* att  = (const float*)d_in[3];
    const float* bias = (const float*)d_in[4];
    float* out = (float*)d_out;

    const int N = in_sizes[0] / FDIM;
    const int E = in_sizes[1] / 2;
    const int* src = ei;        // aggregation target i
    const int* dst = ei + E;    // neighbor j

    const int nblk = (N + SCAN_CHUNK - 1) / SCAN_CHUNK;

    gemm_kernel<<<(N + 127) / 128, 256>>>(x, w, att, N);
    zero_cnt_kernel<<<(N + 255) / 256, 256>>>(N);
    hist_kernel<<<(E + 255) / 256, 256>>>(src, dst, E);
    scan_partial_kernel<<<nblk, 256>>>(N);
    scan_top_kernel<<<1, 128>>>(nblk);
    scan_low_kernel<<<nblk, 256>>>(N);
    scatter_kernel<<<(E + 255) / 256, 256>>>(src, dst, E);
    agg_kernel<<<(N + 7) / 8, 256>>>(bias, out, N);
}